// round 10
// baseline (speedup 1.0000x reference)
#include <cuda_runtime.h>
#include <cuda_bf16.h>
#include <math.h>
#include <stdint.h>

#define Bz   4
#define Sz   4096
#define Dz   1024
#define Hn   16
#define En   8
#define HIDz 4096
#define Tz   (Bz*Sz)
#define MAXROWS (2*Tz + En*128)

// smem tile geometry: 128 rows x 32 k (bf16, 64B data padded to 80B rows)
#define RSTR   80
#define SPLITB (128*RSTR)        // 10240 B per split tile
#define STAGEB (4*SPLITB)        // AH AL BH BL
#define NST    2
#define DSMEM  (NST*STAGEB)      // 81920 B -> 2 CTAs/SM

typedef unsigned short u16;

// ---------------- scratch (static device globals; no allocs allowed) -------
__device__ float g_XC  [(size_t)Tz*Dz];
__device__ float g_QKV [(size_t)Tz*3*Dz];
__device__ float g_PROJ[(size_t)Tz*Dz];
__device__ float g_X1  [(size_t)Tz*Dz];
__device__ float g_YB  [(size_t)Tz*2*Dz];
// bf16 hi/lo pair operands
__device__ u16 g_XbH [(size_t)Tz*Dz];      __device__ u16 g_XbL [(size_t)Tz*Dz];
__device__ u16 g_XCbH[(size_t)Tz*Dz];      __device__ u16 g_XCbL[(size_t)Tz*Dz];
__device__ u16 g_AObH[(size_t)Tz*Dz];      __device__ u16 g_AObL[(size_t)Tz*Dz];
__device__ u16 g_X1bH[(size_t)Tz*Dz];      __device__ u16 g_X1bL[(size_t)Tz*Dz];
__device__ u16 g_HbH [(size_t)MAXROWS*HIDz]; __device__ u16 g_HbL [(size_t)MAXROWS*HIDz];
__device__ u16 g_WINbH [(size_t)3*Dz*Dz];  __device__ u16 g_WINbL [(size_t)3*Dz*Dz];
__device__ u16 g_WOUTbH[(size_t)Dz*Dz];    __device__ u16 g_WOUTbL[(size_t)Dz*Dz];
__device__ u16 g_WCVbH [(size_t)Dz*3*Dz];  __device__ u16 g_WCVbL [(size_t)Dz*3*Dz];
__device__ u16 g_W1bH[(size_t)En*HIDz*Dz]; __device__ u16 g_W1bL[(size_t)En*HIDz*Dz];
__device__ u16 g_W2bH[(size_t)En*Dz*HIDz]; __device__ u16 g_W2bL[(size_t)En*Dz*HIDz];
// routing
__device__ int   g_counts[En];
__device__ int   g_offsets[En];
__device__ int   g_cursor[En];
__device__ int   g_rows_token[MAXROWS];
__device__ float g_rows_w[MAXROWS];
__device__ int   g_rows_slot[MAXROWS];
__device__ int   g_te[Tz][2];
__device__ float g_tw[Tz][2];

// ---------------- helpers ---------------------------------------------------
__device__ __forceinline__ float warpsum(float v) {
    #pragma unroll
    for (int o = 16; o; o >>= 1) v += __shfl_xor_sync(0xffffffffu, v, o);
    return v;
}
// split two floats into packed bf16 hi / lo words
__device__ __forceinline__ void split2(float x, float y, uint32_t& h, uint32_t& l) {
    __nv_bfloat16 hx = __float2bfloat16(x), hy = __float2bfloat16(y);
    __nv_bfloat16 lx = __float2bfloat16(x - __bfloat162float(hx));
    __nv_bfloat16 ly = __float2bfloat16(y - __bfloat162float(hy));
    h = (uint32_t)__bfloat16_as_ushort(hx) | ((uint32_t)__bfloat16_as_ushort(hy) << 16);
    l = (uint32_t)__bfloat16_as_ushort(lx) | ((uint32_t)__bfloat16_as_ushort(ly) << 16);
}
__device__ __forceinline__ uint32_t smem_u32(const void* p) {
    uint32_t a;
    asm("{ .reg .u64 t; cvta.to.shared.u64 t, %1; cvt.u32.u64 %0, t; }"
        : "=r"(a) : "l"(p));
    return a;
}
__device__ __forceinline__ void cpa16(uint32_t d, const void* s, int sz) {
    asm volatile("cp.async.cg.shared.global [%0], [%1], 16, %2;"
                 :: "r"(d), "l"(s), "r"(sz) : "memory");
}
#define CP_COMMIT() asm volatile("cp.async.commit_group;" ::: "memory")
#define CP_WAIT(n)  asm volatile("cp.async.wait_group %0;" :: "n"(n) : "memory")

__device__ __forceinline__ void ldsm4(uint32_t* r, uint32_t a) {
    asm volatile("ldmatrix.sync.aligned.m8n8.x4.shared.b16 {%0,%1,%2,%3}, [%4];"
                 : "=r"(r[0]), "=r"(r[1]), "=r"(r[2]), "=r"(r[3]) : "r"(a));
}
__device__ __forceinline__ void hmma(float* d, const uint32_t* a, const uint32_t* b) {
    asm volatile(
        "mma.sync.aligned.m16n8k16.row.col.f32.bf16.bf16.f32 "
        "{%0,%1,%2,%3}, {%4,%5,%6,%7}, {%8,%9}, {%0,%1,%2,%3};"
        : "+f"(d[0]), "+f"(d[1]), "+f"(d[2]), "+f"(d[3])
        : "r"(a[0]), "r"(a[1]), "r"(a[2]), "r"(a[3]), "r"(b[0]), "r"(b[1]));
}

// ---------------- prep kernels ---------------------------------------------
__global__ void k_zero_counts() {
    if (threadIdx.x < En) g_counts[threadIdx.x] = 0;
}
// elementwise f32 -> bf16 pair (4 elems/thread)
__global__ void k_cvt(const float* __restrict__ in, u16* __restrict__ H,
                      u16* __restrict__ L, int n4) {
    int i = blockIdx.x * 256 + threadIdx.x;
    if (i >= n4) return;
    float4 v = ((const float4*)in)[i];
    uint32_t h0, l0, h1, l1;
    split2(v.x, v.y, h0, l0);
    split2(v.z, v.w, h1, l1);
    ((uint2*)H)[i] = make_uint2(h0, h1);
    ((uint2*)L)[i] = make_uint2(l0, l1);
}
// conv weight: WCV[n][tap*D+di] = conv_w[n][di][tap]
__global__ void k_convw(const float* __restrict__ cw) {
    int n = blockIdx.y;
    int k2 = (blockIdx.x * 256 + threadIdx.x) * 2;   // 0..3070
    int tap = k2 >> 10, di = k2 & 1023;
    float a = cw[((size_t)n * Dz + di) * 3 + tap];
    float b = cw[((size_t)n * Dz + di + 1) * 3 + tap];
    uint32_t h, l;
    split2(a, b, h, l);
    size_t o = (size_t)n * 3 * Dz + k2;
    *(uint32_t*)(g_WCVbH + o) = h;
    *(uint32_t*)(g_WCVbL + o) = l;
}
// batched transpose + split: in [bz][R][C] -> out [bz][C][R] pairs
__global__ void k_wtrans(const float* __restrict__ in, u16* __restrict__ H,
                         u16* __restrict__ L, int R, int C) {
    __shared__ float tile[32][33];
    int bz = blockIdx.z;
    int rc = blockIdx.y * 32, cc = blockIdx.x * 32;
    int tx = threadIdx.x, ty = threadIdx.y;
    #pragma unroll
    for (int i = 0; i < 4; i++)
        tile[ty + i * 8][tx] = in[((size_t)bz * R + rc + ty + i * 8) * C + cc + tx];
    __syncthreads();
    int rp = tx & 15;
    int c0 = (tx >> 4) + ty * 2;
    #pragma unroll
    for (int i = 0; i < 2; i++) {
        int c = c0 + i * 16;
        float a = tile[2 * rp][c], b = tile[2 * rp + 1][c];
        uint32_t h, l;
        split2(a, b, h, l);
        size_t o = ((size_t)bz * C + cc + c) * R + rc + 2 * rp;
        *(uint32_t*)(H + o) = h;
        *(uint32_t*)(L + o) = l;
    }
}

// ---------------- bf16-split tensor-core GEMM ------------------------------
// 128 threads, 4 warps, warp tile 64x64 (CTA 128x128), 2-stage cp.async
// AM: 0 dense pair A, 1 conv gather (Xb), 2 moe1 token gather (X1b), 3 moe2 (Hb)
// NT: 3 or 4 split products
// EM: 0 f32 C, 1 relu -> Hb pairs, 2 scale -> YB f32, 3 f32 XC + XCb pairs
template<int AM, int NT, int EM>
__global__ void __launch_bounds__(128, 2)
k_gemm(const u16* __restrict__ AHg, const u16* __restrict__ ALg,
       const u16* __restrict__ BHg, const u16* __restrict__ BLg,
       const float* __restrict__ bias, float* __restrict__ C,
       int K, int ldc) {
    int e = 0, cnt = 0, off = 0;
    int bm = blockIdx.y * 128, bn = blockIdx.x * 128;
    if (AM >= 2) {
        e = blockIdx.z;
        cnt = g_counts[e];
        off = g_offsets[e];
        if (bm >= cnt) return;
        size_t wsz = (size_t)Dz * HIDz;
        BHg += (size_t)e * wsz;
        BLg += (size_t)e * wsz;
        bias += (size_t)e * ((EM == 1) ? HIDz : Dz);
    }
    extern __shared__ uint8_t dsm[];
    uint32_t sb = smem_u32(dsm);
    int tid = threadIdx.x;
    int wid = tid >> 5, lane = tid & 31;
    int wm = wid >> 1, wn = wid & 1;          // warp tile 64x64

    // staging: thread = one row (0..127), 4x16B chunks per split tile
    int row = tid;
    size_t aoff = 0;
    bool arow_ok = true;
    if (AM == 0) {
        aoff = (size_t)(bm + row) * K;
    } else if (AM == 2) {
        int ri = bm + row;
        int tok = (ri < cnt) ? g_rows_token[off + ri] : -1;
        arow_ok = (tok >= 0);
        aoff = (size_t)(tok < 0 ? 0 : tok) * Dz;
    } else if (AM == 3) {
        arow_ok = (bm + row < cnt);
        aoff = (size_t)(off + bm + (arow_ok ? row : 0)) * K;
    }
    int tt = bm + row;
    int sq = tt & (Sz - 1);
    size_t boff = (size_t)(bn + row) * K;

    auto do_stage = [&](int kt, int buf) {
        int k0 = kt * 32;
        size_t asrc;
        int asz;
        if (AM == 1) {
            int tap = k0 >> 10;
            int srow = sq + tap - 1;
            bool ok = ((unsigned)srow < (unsigned)Sz);
            asz = ok ? 16 : 0;
            asrc = (size_t)(tt + tap - 1) * Dz + (k0 & (Dz - 1));
            if (!ok) asrc = 0;
        } else {
            asz = arow_ok ? 16 : 0;
            asrc = aoff + k0;
        }
        uint32_t d = sb + buf * STAGEB + row * RSTR;
        size_t bsrc = boff + k0;
        #pragma unroll
        for (int cbk = 0; cbk < 4; cbk++) {
            cpa16(d + cbk * 16,              AHg + asrc + cbk * 8, asz);
            cpa16(d + SPLITB + cbk * 16,     ALg + asrc + cbk * 8, asz);
            cpa16(d + 2 * SPLITB + cbk * 16, BHg + bsrc + cbk * 8, 16);
            cpa16(d + 3 * SPLITB + cbk * 16, BLg + bsrc + cbk * 8, 16);
        }
        CP_COMMIT();
    };

    float acc[4][8][4] = {};
    int nkt = K / 32;
    do_stage(0, 0);
    do_stage(1, 1);
    for (int kt = 0; kt < nkt; kt++) {
        int buf = kt & 1;
        if (kt + 1 < nkt) { CP_WAIT(1); }
        else              { CP_WAIT(0); }
        __syncthreads();
        uint32_t sA = sb + buf * STAGEB;
        uint32_t sB = sA + 2 * SPLITB;
        #pragma unroll
        for (int ks = 0; ks < 2; ks++) {
            int kb = ks * 32 + (lane >> 4) * 16;
            uint32_t bh[4][4], bl[4][4];
            #pragma unroll
            for (int p = 0; p < 4; p++) {
                uint32_t a = sB + (wn * 64 + p * 16 + (lane & 15)) * RSTR + kb;
                ldsm4(bh[p], a);
                ldsm4(bl[p], a + SPLITB);
            }
            #pragma unroll
            for (int mi = 0; mi < 4; mi++) {
                uint32_t ah[4], al[4];
                uint32_t a = sA + (wm * 64 + mi * 16 + (lane & 15)) * RSTR + kb;
                ldsm4(ah, a);
                ldsm4(al, a + SPLITB);
                #pragma unroll
                for (int ni = 0; ni < 8; ni++) {
                    int p = ni >> 1, q = ni & 1;
                    uint32_t B0[2] = { bh[p][q], bh[p][q + 2] };
                    uint32_t B1[2] = { bl[p][q], bl[p][q + 2] };
                    hmma(acc[mi][ni], ah, B0);
                    hmma(acc[mi][ni], ah, B1);
                    hmma(acc[mi][ni], al, B0);
                    if (NT == 4) hmma(acc[mi][ni], al, B1);
                }
            }
        }
        __syncthreads();
        if (kt + 2 < nkt) do_stage(kt + 2, buf);
    }

    // ---- epilogue (warp tile 64x64) ----
    #pragma unroll
    for (int mi = 0; mi < 4; mi++) {
        #pragma unroll
        for (int rh = 0; rh < 2; rh++) {
            int lrow = wm * 64 + mi * 16 + (lane >> 2) + rh * 8;
            int grow = bm + lrow;
            int tok = 0, slot = 0;
            float wgt = 0.f;
            if (EM == 2) {
                if (grow < cnt) {
                    int rg = off + grow;
                    tok = g_rows_token[rg];
                    slot = g_rows_slot[rg];
                    wgt = g_rows_w[rg];
                }
            }
            #pragma unroll
            for (int ni = 0; ni < 8; ni++) {
                int col = bn + wn * 64 + ni * 8 + (lane & 3) * 2;
                float vx = acc[mi][ni][rh * 2 + 0] + bias[col];
                float vy = acc[mi][ni][rh * 2 + 1] + bias[col + 1];
                if (EM == 0) {
                    *(float2*)(C + (size_t)grow * ldc + col) = make_float2(vx, vy);
                } else if (EM == 3) {
                    size_t o = (size_t)grow * Dz + col;
                    *(float2*)(C + o) = make_float2(vx, vy);
                    uint32_t h, l;
                    split2(vx, vy, h, l);
                    *(uint32_t*)(g_XCbH + o) = h;
                    *(uint32_t*)(g_XCbL + o) = l;
                } else if (EM == 1) {
                    if (grow < cnt) {
                        vx = fmaxf(vx, 0.f);
                        vy = fmaxf(vy, 0.f);
                        uint32_t h, l;
                        split2(vx, vy, h, l);
                        size_t o = (size_t)(off + grow) * HIDz + col;
                        *(uint32_t*)(g_HbH + o) = h;
                        *(uint32_t*)(g_HbL + o) = l;
                    }
                } else {  // EM == 2
                    if (grow < cnt) {
                        size_t o = ((size_t)tok * 2 + slot) * Dz + col;
                        *(float2*)(g_YB + o) = make_float2(wgt * vx, wgt * vy);
                    }
                }
            }
        }
    }
}

// ---------------- tiny attention (seq axis = B = 4) ------------------------
__global__ void k_attn() {
    int wg = blockIdx.x * 8 + (threadIdx.x >> 5);
    int lane = threadIdx.x & 31;
    int h = wg & (Hn - 1);
    int n = wg >> 4;
    const float scale = 0.125f;
    float2 q[Bz], k[Bz], v[Bz];
    #pragma unroll
    for (int li = 0; li < Bz; li++) {
        size_t base = ((size_t)li * Sz + n) * (3 * Dz) + h * 64 + lane * 2;
        q[li] = *(const float2*)(g_QKV + base);
        k[li] = *(const float2*)(g_QKV + base + Dz);
        v[li] = *(const float2*)(g_QKV + base + 2 * Dz);
    }
    float p[Bz][Bz];
    #pragma unroll
    for (int li = 0; li < Bz; li++)
        #pragma unroll
        for (int m = 0; m < Bz; m++) {
            float tv = q[li].x * k[m].x + q[li].y * k[m].y;
            tv = warpsum(tv);
            p[li][m] = tv * scale;
        }
    #pragma unroll
    for (int li = 0; li < Bz; li++) {
        float mx = fmaxf(fmaxf(p[li][0], p[li][1]), fmaxf(p[li][2], p[li][3]));
        float sum = 0.f;
        #pragma unroll
        for (int m = 0; m < Bz; m++) { p[li][m] = expf(p[li][m] - mx); sum += p[li][m]; }
        float inv = 1.f / sum;
        #pragma unroll
        for (int m = 0; m < Bz; m++) p[li][m] *= inv;
    }
    #pragma unroll
    for (int li = 0; li < Bz; li++) {
        float2 o = make_float2(0.f, 0.f);
        #pragma unroll
        for (int m = 0; m < Bz; m++) {
            o.x += p[li][m] * v[m].x;
            o.y += p[li][m] * v[m].y;
        }
        uint32_t hw, lw;
        split2(o.x, o.y, hw, lw);
        size_t idx = ((size_t)li * Sz + n) * Dz + h * 64 + lane * 2;
        *(uint32_t*)(g_AObH + idx) = hw;
        *(uint32_t*)(g_AObL + idx) = lw;
    }
}

// ---------------- LayerNorm kernels ---------------------------------------
// X1 = LN(XC + PROJ); also emits X1 bf16 pairs
__global__ void k_ln_add2(const float* __restrict__ A, const float* __restrict__ Bb,
                          const float* __restrict__ g, const float* __restrict__ be,
                          float* __restrict__ out) {
    int t = blockIdx.x, tid = threadIdx.x;
    float4 v = ((const float4*)(A + (size_t)t * Dz))[tid];
    float4 w = ((const float4*)(Bb + (size_t)t * Dz))[tid];
    v.x += w.x; v.y += w.y; v.z += w.z; v.w += w.w;
    float s = v.x + v.y + v.z + v.w;
    float q = v.x * v.x + v.y * v.y + v.z * v.z + v.w * v.w;
    s = warpsum(s); q = warpsum(q);
    __shared__ float ss[8], sq[8];
    int wid = tid >> 5;
    if ((tid & 31) == 0) { ss[wid] = s; sq[wid] = q; }
    __syncthreads();
    float S = 0.f, Q = 0.f;
    #pragma unroll
    for (int i = 0; i < 8; i++) { S += ss[i]; Q += sq[i]; }
    float mean = S * (1.f / Dz);
    float var  = Q * (1.f / Dz) - mean * mean;
    float rstd = rsqrtf(var + 1e-5f);
    float4 gg = ((const float4*)g)[tid];
    float4 bb = ((const float4*)be)[tid];
    float4 o;
    o.x = (v.x - mean) * rstd * gg.x + bb.x;
    o.y = (v.y - mean) * rstd * gg.y + bb.y;
    o.z = (v.z - mean) * rstd * gg.z + bb.z;
    o.w = (v.w - mean) * rstd * gg.w + bb.w;
    ((float4*)(out + (size_t)t * Dz))[tid] = o;
    uint32_t h0, l0, h1, l1;
    split2(o.x, o.y, h0, l0);
    split2(o.z, o.w, h1, l1);
    ((uint2*)(g_X1bH + (size_t)t * Dz))[tid] = make_uint2(h0, h1);
    ((uint2*)(g_X1bL + (size_t)t * Dz))[tid] = make_uint2(l0, l1);
}

__global__ void k_ln_add3(const float* __restrict__ A,
                          const float* __restrict__ g, const float* __restrict__ be,
                          float* __restrict__ out) {
    int t = blockIdx.x, tid = threadIdx.x;
    float4 v  = ((const float4*)(A + (size_t)t * Dz))[tid];
    float4 y0 = ((const float4*)(g_YB + (size_t)t * 2 * Dz))[tid];
    float4 y1 = ((const float4*)(g_YB + (size_t)t * 2 * Dz + Dz))[tid];
    v.x += y0.x + y1.x; v.y += y0.y + y1.y;
    v.z += y0.z + y1.z; v.w += y0.w + y1.w;
    float s = v.x + v.y + v.z + v.w;
    float q = v.x * v.x + v.y * v.y + v.z * v.z + v.w * v.w;
    s = warpsum(s); q = warpsum(q);
    __shared__ float ss[8], sq[8];
    int wid = tid >> 5;
    if ((tid & 31) == 0) { ss[wid] = s; sq[wid] = q; }
    __syncthreads();
    float S = 0.f, Q = 0.f;
    #pragma unroll
    for (int i = 0; i < 8; i++) { S += ss[i]; Q += sq[i]; }
    float mean = S * (1.f / Dz);
    float var  = Q * (1.f / Dz) - mean * mean;
    float rstd = rsqrtf(var + 1e-5f);
    float4 gg = ((const float4*)g)[tid];
    float4 bb = ((const float4*)be)[tid];
    float4 o;
    o.x = (v.x - mean) * rstd * gg.x + bb.x;
    o.y = (v.y - mean) * rstd * gg.y + bb.y;
    o.z = (v.z - mean) * rstd * gg.z + bb.z;
    o.w = (v.w - mean) * rstd * gg.w + bb.w;
    ((float4*)(out + (size_t)t * Dz))[tid] = o;
}

// ---------------- MoE routing ---------------------------------------------
__global__ void k_gate(const float* __restrict__ gw, const float* __restrict__ gb) {
    int t = blockIdx.x * 8 + (threadIdx.x >> 5);
    int lane = threadIdx.x & 31;
    float acc[En] = {};
    const float* xr = g_X1 + (size_t)t * Dz;
    for (int d = lane; d < Dz; d += 32) {
        float xv = xr[d];
        #pragma unroll
        for (int e = 0; e < En; e++) acc[e] += xv * gw[d * En + e];
    }
    #pragma unroll
    for (int e = 0; e < En; e++) acc[e] = warpsum(acc[e]);
    if (lane == 0) {
        #pragma unroll
        for (int e = 0; e < En; e++) acc[e] += gb[e];
        int e0 = 0; float b0 = acc[0];
        #pragma unroll
        for (int e = 1; e < En; e++) if (acc[e] > b0) { b0 = acc[e]; e0 = e; }
        int e1 = -1; float b1v = -1e30f;
        #pragma unroll
        for (int e = 0; e < En; e++)
            if (e != e0 && acc[e] > b1v) { b1v = acc[e]; e1 = e; }
        float x1 = expf(b1v - b0);
        float inv = 1.f / (1.f + x1);
        g_te[t][0] = e0; g_te[t][1] = e1;
        g_tw[t][0] = inv; g_tw[t][1] = x1 * inv;
        atomicAdd(&g_counts[e0], 1);
        atomicAdd(&g_counts[e1], 1);
    }
}

__global__ void k_offsets() {
    if (threadIdx.x == 0) {
        int off = 0;
        for (int e = 0; e < En; e++) {
            g_offsets[e] = off;
            off += ((g_counts[e] + 127) >> 7) << 7;
            g_cursor[e] = 0;
        }
    }
}

__global__ void k_scatter() {
    int t = blockIdx.x * 256 + threadIdx.x;
    if (t >= Tz) return;
    #pragma unroll
    for (int slot = 0; slot < 2; slot++) {
        int e = g_te[t][slot];
        int pos = atomicAdd(&g_cursor[e], 1);
        int row = g_offsets[e] + pos;
        g_rows_token[row] = t;
        g_rows_w[row] = g_tw[t][slot];
        g_rows_slot[row] = slot;
    }
}

// ---------------- launch ---------------------------------------------------
extern "C" void kernel_launch(void* const* d_in, const int* in_sizes, int n_in,
                              void* d_out, int out_size) {
    const float* x          = (const float*)d_in[0];
    const float* conv_w     = (const float*)d_in[1];
    const float* conv_b     = (const float*)d_in[2];
    const float* in_proj_w  = (const float*)d_in[3];
    const float* in_proj_b  = (const float*)d_in[4];
    const float* out_proj_w = (const float*)d_in[5];
    const float* out_proj_b = (const float*)d_in[6];
    const float* ln1_g      = (const float*)d_in[7];
    const float* ln1_b      = (const float*)d_in[8];
    const float* gate_w     = (const float*)d_in[9];
    const float* gate_b     = (const float*)d_in[10];
    const float* w1         = (const float*)d_in[11];
    const float* b1         = (const float*)d_in[12];
    const float* w2         = (const float*)d_in[13];
    const float* b2         = (const float*)d_in[14];
    const float* ln2_g      = (const float*)d_in[15];
    const float* ln2_b      = (const float*)d_in[16];
    float* out = (float*)d_out;

    float *pXC, *pQKV, *pPROJ, *pX1;
    cudaGetSymbolAddress((void**)&pXC,   g_XC);
    cudaGetSymbolAddress((void**)&pQKV,  g_QKV);
    cudaGetSymbolAddress((void**)&pPROJ, g_PROJ);
    cudaGetSymbolAddress((void**)&pX1,   g_X1);
    u16 *pXbH, *pXbL, *pXCbH, *pXCbL, *pAObH, *pAObL, *pX1bH, *pX1bL, *pHbH, *pHbL;
    u16 *pWINbH, *pWINbL, *pWOUTbH, *pWOUTbL, *pWCVbH, *pWCVbL;
    u16 *pW1bH, *pW1bL, *pW2bH, *pW2bL;
    cudaGetSymbolAddress((void**)&pXbH, g_XbH);   cudaGetSymbolAddress((void**)&pXbL, g_XbL);
    cudaGetSymbolAddress((void**)&pXCbH, g_XCbH); cudaGetSymbolAddress((void**)&pXCbL, g_XCbL);
    cudaGetSymbolAddress((void**)&pAObH, g_AObH); cudaGetSymbolAddress((void**)&pAObL, g_AObL);
    cudaGetSymbolAddress((void**)&pX1bH, g_X1bH); cudaGetSymbolAddress((void**)&pX1bL, g_X1bL);
    cudaGetSymbolAddress((void**)&pHbH, g_HbH);   cudaGetSymbolAddress((void**)&pHbL, g_HbL);
    cudaGetSymbolAddress((void**)&pWINbH, g_WINbH);   cudaGetSymbolAddress((void**)&pWINbL, g_WINbL);
    cudaGetSymbolAddress((void**)&pWOUTbH, g_WOUTbH); cudaGetSymbolAddress((void**)&pWOUTbL, g_WOUTbL);
    cudaGetSymbolAddress((void**)&pWCVbH, g_WCVbH);   cudaGetSymbolAddress((void**)&pWCVbL, g_WCVbL);
    cudaGetSymbolAddress((void**)&pW1bH, g_W1bH);     cudaGetSymbolAddress((void**)&pW1bL, g_W1bL);
    cudaGetSymbolAddress((void**)&pW2bH, g_W2bH);     cudaGetSymbolAddress((void**)&pW2bL, g_W2bL);

    cudaFuncSetAttribute(k_gemm<1,4,3>, cudaFuncAttributeMaxDynamicSharedMemorySize, DSMEM);
    cudaFuncSetAttribute(k_gemm<0,4,0>, cudaFuncAttributeMaxDynamicSharedMemorySize, DSMEM);
    cudaFuncSetAttribute(k_gemm<2,3,1>, cudaFuncAttributeMaxDynamicSharedMemorySize, DSMEM);
    cudaFuncSetAttribute(k_gemm<3,3,2>, cudaFuncAttributeMaxDynamicSharedMemorySize, DSMEM);

    k_zero_counts<<<1, 32>>>();
    // operand prep: f32 -> bf16 hi/lo
    k_cvt<<<(Tz * Dz / 4) / 256, 256>>>(x, pXbH, pXbL, Tz * Dz / 4);
    k_cvt<<<(3 * Dz * Dz / 4) / 256, 256>>>(in_proj_w, pWINbH, pWINbL, 3 * Dz * Dz / 4);
    k_cvt<<<(Dz * Dz / 4) / 256, 256>>>(out_proj_w, pWOUTbH, pWOUTbL, Dz * Dz / 4);
    k_convw<<<dim3(6, Dz), 256>>>(conv_w);
    dim3 tb(32, 8);
    k_wtrans<<<dim3(HIDz / 32, Dz / 32, En), tb>>>(w1, pW1bH, pW1bL, Dz, HIDz);
    k_wtrans<<<dim3(Dz / 32, HIDz / 32, En), tb>>>(w2, pW2bH, pW2bL, HIDz, Dz);
    // conv  (M=T, N=1024, K=3072): f32 XC + XCb pairs
    k_gemm<1,4,3><<<dim3(8, 128), 128, DSMEM>>>(pXbH, pXbL, pWCVbH, pWCVbL,
                                                conv_b, pXC, 3 * Dz, Dz);
    // qkv   (M=T, N=3072, K=1024)
    k_gemm<0,4,0><<<dim3(24, 128), 128, DSMEM>>>(pXCbH, pXCbL, pWINbH, pWINbL,
                                                 in_proj_b, pQKV, Dz, 3 * Dz);
    // attention (tiny seq=B=4) -> AOb pairs
    k_attn<<<(Sz * Hn) / 8, 256>>>();
    // out_proj (M=T, N=1024, K=1024)
    k_gemm<0,4,0><<<dim3(8, 128), 128, DSMEM>>>(pAObH, pAObL, pWOUTbH, pWOUTbL,
                                                out_proj_b, pPROJ, Dz, Dz);
    // residual + LN1 (emits X1 f32 + pairs)
    k_ln_add2<<<Tz, 256>>>(pXC, pPROJ, ln1_g, ln1_b, pX1);
    // MoE routing
    k_gate<<<Tz / 8, 256>>>(gate_w, gate_b);
    k_offsets<<<1, 32>>>();
    k_scatter<<<Tz / 256, 256>>>();
    // grouped expert GEMMs
    k_gemm<2,3,1><<<dim3(32, 128, En), 128, DSMEM>>>(pX1bH, pX1bL, pW1bH, pW1bL,
                                                     b1, nullptr, Dz, 0);
    k_gemm<3,3,2><<<dim3(8, 128, En), 128, DSMEM>>>(pHbH, pHbL, pW2bH, pW2bL,
                                                    b2, nullptr, HIDz, 0);
    // residual + LN2 -> output
    k_ln_add3<<<Tz, 256>>>(pX1, ln2_g, ln2_b, out);
}

// round 15
// speedup vs baseline: 1.2431x; 1.2431x over previous
#include <cuda_runtime.h>
#include <cuda_bf16.h>
#include <math.h>
#include <stdint.h>

#define Bz   4
#define Sz   4096
#define Dz   1024
#define Hn   16
#define En   8
#define HIDz 4096
#define Tz   (Bz*Sz)
#define MAXROWS (2*Tz + En*128)

// smem tile geometry: 128 rows x 32 k (bf16, 64B data padded to 80B rows)
#define RSTR   80
#define SPLITB (128*RSTR)        // 10240 B per split tile
#define STAGEB (4*SPLITB)        // AH AL BH BL
#define NST    2
#define DSMEM  (NST*STAGEB)      // 81920 B -> 2 CTAs/SM

typedef unsigned short u16;

// ---------------- scratch (static device globals; no allocs allowed) -------
__device__ float g_XC  [(size_t)Tz*Dz];
__device__ float g_QKV [(size_t)Tz*3*Dz];
__device__ float g_PROJ[(size_t)Tz*Dz];
__device__ float g_X1  [(size_t)Tz*Dz];
__device__ float g_YB  [(size_t)Tz*2*Dz];
// bf16 hi/lo pair operands
__device__ u16 g_XbH [(size_t)Tz*Dz];      __device__ u16 g_XbL [(size_t)Tz*Dz];
__device__ u16 g_XCbH[(size_t)Tz*Dz];      __device__ u16 g_XCbL[(size_t)Tz*Dz];
__device__ u16 g_AObH[(size_t)Tz*Dz];      __device__ u16 g_AObL[(size_t)Tz*Dz];
__device__ u16 g_X1bH[(size_t)Tz*Dz];      __device__ u16 g_X1bL[(size_t)Tz*Dz];
__device__ u16 g_HbH [(size_t)MAXROWS*HIDz]; __device__ u16 g_HbL [(size_t)MAXROWS*HIDz];
__device__ u16 g_WINbH [(size_t)3*Dz*Dz];  __device__ u16 g_WINbL [(size_t)3*Dz*Dz];
__device__ u16 g_WOUTbH[(size_t)Dz*Dz];    __device__ u16 g_WOUTbL[(size_t)Dz*Dz];
__device__ u16 g_WCVbH [(size_t)Dz*3*Dz];  __device__ u16 g_WCVbL [(size_t)Dz*3*Dz];
__device__ u16 g_W1bH[(size_t)En*HIDz*Dz]; __device__ u16 g_W1bL[(size_t)En*HIDz*Dz];
__device__ u16 g_W2bH[(size_t)En*Dz*HIDz]; __device__ u16 g_W2bL[(size_t)En*Dz*HIDz];
// routing
__device__ int   g_counts[En];
__device__ int   g_offsets[En];
__device__ int   g_cursor[En];
__device__ int   g_rows_token[MAXROWS];
__device__ float g_rows_w[MAXROWS];
__device__ int   g_rows_slot[MAXROWS];
__device__ int   g_te[Tz][2];
__device__ float g_tw[Tz][2];

// ---------------- helpers ---------------------------------------------------
__device__ __forceinline__ float warpsum(float v) {
    #pragma unroll
    for (int o = 16; o; o >>= 1) v += __shfl_xor_sync(0xffffffffu, v, o);
    return v;
}
// split two floats into packed bf16 hi / lo words
__device__ __forceinline__ void split2(float x, float y, uint32_t& h, uint32_t& l) {
    __nv_bfloat16 hx = __float2bfloat16(x), hy = __float2bfloat16(y);
    __nv_bfloat16 lx = __float2bfloat16(x - __bfloat162float(hx));
    __nv_bfloat16 ly = __float2bfloat16(y - __bfloat162float(hy));
    h = (uint32_t)__bfloat16_as_ushort(hx) | ((uint32_t)__bfloat16_as_ushort(hy) << 16);
    l = (uint32_t)__bfloat16_as_ushort(lx) | ((uint32_t)__bfloat16_as_ushort(ly) << 16);
}
__device__ __forceinline__ uint32_t smem_u32(const void* p) {
    uint32_t a;
    asm("{ .reg .u64 t; cvta.to.shared.u64 t, %1; cvt.u32.u64 %0, t; }"
        : "=r"(a) : "l"(p));
    return a;
}
__device__ __forceinline__ void cpa16(uint32_t d, const void* s, int sz) {
    asm volatile("cp.async.cg.shared.global [%0], [%1], 16, %2;"
                 :: "r"(d), "l"(s), "r"(sz) : "memory");
}
#define CP_COMMIT() asm volatile("cp.async.commit_group;" ::: "memory")
#define CP_WAIT(n)  asm volatile("cp.async.wait_group %0;" :: "n"(n) : "memory")

__device__ __forceinline__ void ldsm4(uint32_t* r, uint32_t a) {
    asm volatile("ldmatrix.sync.aligned.m8n8.x4.shared.b16 {%0,%1,%2,%3}, [%4];"
                 : "=r"(r[0]), "=r"(r[1]), "=r"(r[2]), "=r"(r[3]) : "r"(a));
}
__device__ __forceinline__ void hmma(float* d, const uint32_t* a, const uint32_t* b) {
    asm volatile(
        "mma.sync.aligned.m16n8k16.row.col.f32.bf16.bf16.f32 "
        "{%0,%1,%2,%3}, {%4,%5,%6,%7}, {%8,%9}, {%0,%1,%2,%3};"
        : "+f"(d[0]), "+f"(d[1]), "+f"(d[2]), "+f"(d[3])
        : "r"(a[0]), "r"(a[1]), "r"(a[2]), "r"(a[3]), "r"(b[0]), "r"(b[1]));
}

// ---------------- prep kernels ---------------------------------------------
__global__ void k_zero_counts() {
    if (threadIdx.x < En) g_counts[threadIdx.x] = 0;
}
// elementwise f32 -> bf16 pair (4 elems/thread)
__global__ void k_cvt(const float* __restrict__ in, u16* __restrict__ H,
                      u16* __restrict__ L, int n4) {
    int i = blockIdx.x * 256 + threadIdx.x;
    if (i >= n4) return;
    float4 v = ((const float4*)in)[i];
    uint32_t h0, l0, h1, l1;
    split2(v.x, v.y, h0, l0);
    split2(v.z, v.w, h1, l1);
    ((uint2*)H)[i] = make_uint2(h0, h1);
    ((uint2*)L)[i] = make_uint2(l0, l1);
}
// conv weight: WCV[n][tap*D+di] = conv_w[n][di][tap]
__global__ void k_convw(const float* __restrict__ cw) {
    int n = blockIdx.y;
    int k2 = (blockIdx.x * 256 + threadIdx.x) * 2;   // 0..3070
    int tap = k2 >> 10, di = k2 & 1023;
    float a = cw[((size_t)n * Dz + di) * 3 + tap];
    float b = cw[((size_t)n * Dz + di + 1) * 3 + tap];
    uint32_t h, l;
    split2(a, b, h, l);
    size_t o = (size_t)n * 3 * Dz + k2;
    *(uint32_t*)(g_WCVbH + o) = h;
    *(uint32_t*)(g_WCVbL + o) = l;
}
// batched transpose + split: in [bz][R][C] -> out [bz][C][R] pairs
__global__ void k_wtrans(const float* __restrict__ in, u16* __restrict__ H,
                         u16* __restrict__ L, int R, int C) {
    __shared__ float tile[32][33];
    int bz = blockIdx.z;
    int rc = blockIdx.y * 32, cc = blockIdx.x * 32;
    int tx = threadIdx.x, ty = threadIdx.y;
    #pragma unroll
    for (int i = 0; i < 4; i++)
        tile[ty + i * 8][tx] = in[((size_t)bz * R + rc + ty + i * 8) * C + cc + tx];
    __syncthreads();
    int rp = tx & 15;
    int c0 = (tx >> 4) + ty * 2;
    #pragma unroll
    for (int i = 0; i < 2; i++) {
        int c = c0 + i * 16;
        float a = tile[2 * rp][c], b = tile[2 * rp + 1][c];
        uint32_t h, l;
        split2(a, b, h, l);
        size_t o = ((size_t)bz * C + cc + c) * R + rc + 2 * rp;
        *(uint32_t*)(H + o) = h;
        *(uint32_t*)(L + o) = l;
    }
}

// ---------------- bf16-split tensor-core GEMM ------------------------------
// 256 threads, 8 warps, warp tile 64x32 (CTA 128x128), 2-stage cp.async
// AM: 0 dense pair A, 1 conv gather (Xb), 2 moe1 token gather (X1b), 3 moe2 (Hb)
// NT: 3 or 4 split products
// EM: 0 f32 C, 1 relu -> Hb pairs, 2 scale -> YB f32, 3 f32 XC + XCb pairs
template<int AM, int NT, int EM>
__global__ void __launch_bounds__(256, 2)
k_gemm(const u16* __restrict__ AHg, const u16* __restrict__ ALg,
       const u16* __restrict__ BHg, const u16* __restrict__ BLg,
       const float* __restrict__ bias, float* __restrict__ C,
       int K, int ldc) {
    int e = 0, cnt = 0, off = 0;
    int bm = blockIdx.y * 128, bn = blockIdx.x * 128;
    if (AM >= 2) {
        e = blockIdx.z;
        cnt = g_counts[e];
        off = g_offsets[e];
        if (bm >= cnt) return;
        size_t wsz = (size_t)Dz * HIDz;
        BHg += (size_t)e * wsz;
        BLg += (size_t)e * wsz;
        bias += (size_t)e * ((EM == 1) ? HIDz : Dz);
    }
    extern __shared__ uint8_t dsm[];
    uint32_t sb = smem_u32(dsm);
    int tid = threadIdx.x;
    int wid = tid >> 5, lane = tid & 31;
    int wm = wid >> 2, wn = wid & 3;          // warp tile 64x32

    // staging mapping: thread -> (row, chunk base)
    int row = tid >> 1;
    int cb  = (tid & 1) * 2;
    size_t aoff = 0;
    bool arow_ok = true;
    if (AM == 0) {
        aoff = (size_t)(bm + row) * K;
    } else if (AM == 2) {
        int ri = bm + row;
        int tok = (ri < cnt) ? g_rows_token[off + ri] : -1;
        arow_ok = (tok >= 0);
        aoff = (size_t)(tok < 0 ? 0 : tok) * Dz;
    } else if (AM == 3) {
        arow_ok = (bm + row < cnt);
        aoff = (size_t)(off + bm + (arow_ok ? row : 0)) * K;
    }
    int tt = bm + row;
    int sq = tt & (Sz - 1);
    size_t boff = (size_t)(bn + row) * K;

    auto do_stage = [&](int kt, int buf) {
        int k0 = kt * 32;
        size_t asrc;
        int asz;
        if (AM == 1) {
            int tap = k0 >> 10;
            int srow = sq + tap - 1;
            bool ok = ((unsigned)srow < (unsigned)Sz);
            asz = ok ? 16 : 0;
            asrc = (size_t)(tt + tap - 1) * Dz + (k0 & (Dz - 1)) + cb * 8;
            if (!ok) asrc = 0;
        } else {
            asz = arow_ok ? 16 : 0;
            asrc = aoff + k0 + cb * 8;
        }
        uint32_t d = sb + buf * STAGEB + row * RSTR + cb * 16;
        cpa16(d,                       AHg + asrc,     asz);
        cpa16(d + 16,                  AHg + asrc + 8, asz);
        cpa16(d + SPLITB,              ALg + asrc,     asz);
        cpa16(d + SPLITB + 16,         ALg + asrc + 8, asz);
        size_t bsrc = boff + k0 + cb * 8;
        cpa16(d + 2 * SPLITB,          BHg + bsrc,     16);
        cpa16(d + 2 * SPLITB + 16,     BHg + bsrc + 8, 16);
        cpa16(d + 3 * SPLITB,          BLg + bsrc,     16);
        cpa16(d + 3 * SPLITB + 16,     BLg + bsrc + 8, 16);
        CP_COMMIT();
    };

    float acc[4][4][4] = {};
    int nkt = K / 32;
    do_stage(0, 0);
    do_stage(1, 1);
    for (int kt = 0; kt < nkt; kt++) {
        int buf = kt & 1;
        if (kt + 1 < nkt) { CP_WAIT(1); }
        else              { CP_WAIT(0); }
        __syncthreads();
        uint32_t sA = sb + buf * STAGEB;
        uint32_t sB = sA + 2 * SPLITB;
        #pragma unroll
        for (int ks = 0; ks < 2; ks++) {
            int kb = ks * 32 + (lane >> 4) * 16;
            uint32_t bh[2][4], bl[2][4];
            #pragma unroll
            for (int p = 0; p < 2; p++) {
                uint32_t a = sB + (wn * 32 + p * 16 + (lane & 15)) * RSTR + kb;
                ldsm4(bh[p], a);
                ldsm4(bl[p], a + SPLITB);
            }
            // software-pipelined A fragments: prefetch mi+1 during mi compute
            uint32_t ahc[4], alc[4], ahn[4], aln[4];
            {
                uint32_t a0 = sA + (wm * 64 + (lane & 15)) * RSTR + kb;
                ldsm4(ahc, a0);
                ldsm4(alc, a0 + SPLITB);
            }
            #pragma unroll
            for (int mi = 0; mi < 4; mi++) {
                if (mi + 1 < 4) {
                    uint32_t a = sA + (wm * 64 + (mi + 1) * 16 + (lane & 15)) * RSTR + kb;
                    ldsm4(ahn, a);
                    ldsm4(aln, a + SPLITB);
                }
                // term-interleaved: sweep ni per product term (acc RAW distance 4)
                #pragma unroll
                for (int ni = 0; ni < 4; ni++) {
                    int p = ni >> 1, q = ni & 1;
                    uint32_t B0[2] = { bh[p][q], bh[p][q + 2] };
                    hmma(acc[mi][ni], ahc, B0);
                }
                #pragma unroll
                for (int ni = 0; ni < 4; ni++) {
                    int p = ni >> 1, q = ni & 1;
                    uint32_t B1[2] = { bl[p][q], bl[p][q + 2] };
                    hmma(acc[mi][ni], ahc, B1);
                }
                #pragma unroll
                for (int ni = 0; ni < 4; ni++) {
                    int p = ni >> 1, q = ni & 1;
                    uint32_t B0[2] = { bh[p][q], bh[p][q + 2] };
                    hmma(acc[mi][ni], alc, B0);
                }
                if (NT == 4) {
                    #pragma unroll
                    for (int ni = 0; ni < 4; ni++) {
                        int p = ni >> 1, q = ni & 1;
                        uint32_t B1[2] = { bl[p][q], bl[p][q + 2] };
                        hmma(acc[mi][ni], alc, B1);
                    }
                }
                #pragma unroll
                for (int r = 0; r < 4; r++) { ahc[r] = ahn[r]; alc[r] = aln[r]; }
            }
        }
        __syncthreads();
        if (kt + 2 < nkt) do_stage(kt + 2, buf);
    }

    // ---- epilogue (warp tile 64x32) ----
    #pragma unroll
    for (int mi = 0; mi < 4; mi++) {
        #pragma unroll
        for (int rh = 0; rh < 2; rh++) {
            int lrow = wm * 64 + mi * 16 + (lane >> 2) + rh * 8;
            int grow = bm + lrow;
            int tok = 0, slot = 0;
            float wgt = 0.f;
            if (EM == 2) {
                if (grow < cnt) {
                    int rg = off + grow;
                    tok = g_rows_token[rg];
                    slot = g_rows_slot[rg];
                    wgt = g_rows_w[rg];
                }
            }
            #pragma unroll
            for (int ni = 0; ni < 4; ni++) {
                int col = bn + wn * 32 + ni * 8 + (lane & 3) * 2;
                float vx = acc[mi][ni][rh * 2 + 0] + bias[col];
                float vy = acc[mi][ni][rh * 2 + 1] + bias[col + 1];
                if (EM == 0) {
                    *(float2*)(C + (size_t)grow * ldc + col) = make_float2(vx, vy);
                } else if (EM == 3) {
                    size_t o = (size_t)grow * Dz + col;
                    *(float2*)(C + o) = make_float2(vx, vy);
                    uint32_t h, l;
                    split2(vx, vy, h, l);
                    *(uint32_t*)(g_XCbH + o) = h;
                    *(uint32_t*)(g_XCbL + o) = l;
                } else if (EM == 1) {
                    if (grow < cnt) {
                        vx = fmaxf(vx, 0.f);
                        vy = fmaxf(vy, 0.f);
                        uint32_t h, l;
                        split2(vx, vy, h, l);
                        size_t o = (size_t)(off + grow) * HIDz + col;
                        *(uint32_t*)(g_HbH + o) = h;
                        *(uint32_t*)(g_HbL + o) = l;
                    }
                } else {  // EM == 2
                    if (grow < cnt) {
                        size_t o = ((size_t)tok * 2 + slot) * Dz + col;
                        *(float2*)(g_YB + o) = make_float2(wgt * vx, wgt * vy);
                    }
                }
            }
        }
    }
}

// ---------------- tiny attention (seq axis = B = 4) ------------------------
__global__ void k_attn() {
    int wg = blockIdx.x * 8 + (threadIdx.x >> 5);
    int lane = threadIdx.x & 31;
    int h = wg & (Hn - 1);
    int n = wg >> 4;
    const float scale = 0.125f;
    float2 q[Bz], k[Bz], v[Bz];
    #pragma unroll
    for (int li = 0; li < Bz; li++) {
        size_t base = ((size_t)li * Sz + n) * (3 * Dz) + h * 64 + lane * 2;
        q[li] = *(const float2*)(g_QKV + base);
        k[li] = *(const float2*)(g_QKV + base + Dz);
        v[li] = *(const float2*)(g_QKV + base + 2 * Dz);
    }
    float p[Bz][Bz];
    #pragma unroll
    for (int li = 0; li < Bz; li++)
        #pragma unroll
        for (int m = 0; m < Bz; m++) {
            float tv = q[li].x * k[m].x + q[li].y * k[m].y;
            tv = warpsum(tv);
            p[li][m] = tv * scale;
        }
    #pragma unroll
    for (int li = 0; li < Bz; li++) {
        float mx = fmaxf(fmaxf(p[li][0], p[li][1]), fmaxf(p[li][2], p[li][3]));
        float sum = 0.f;
        #pragma unroll
        for (int m = 0; m < Bz; m++) { p[li][m] = expf(p[li][m] - mx); sum += p[li][m]; }
        float inv = 1.f / sum;
        #pragma unroll
        for (int m = 0; m < Bz; m++) p[li][m] *= inv;
    }
    #pragma unroll
    for (int li = 0; li < Bz; li++) {
        float2 o = make_float2(0.f, 0.f);
        #pragma unroll
        for (int m = 0; m < Bz; m++) {
            o.x += p[li][m] * v[m].x;
            o.y += p[li][m] * v[m].y;
        }
        uint32_t hw, lw;
        split2(o.x, o.y, hw, lw);
        size_t idx = ((size_t)li * Sz + n) * Dz + h * 64 + lane * 2;
        *(uint32_t*)(g_AObH + idx) = hw;
        *(uint32_t*)(g_AObL + idx) = lw;
    }
}

// ---------------- LayerNorm kernels ---------------------------------------
// X1 = LN(XC + PROJ); also emits X1 bf16 pairs
__global__ void k_ln_add2(const float* __restrict__ A, const float* __restrict__ Bb,
                          const float* __restrict__ g, const float* __restrict__ be,
                          float* __restrict__ out) {
    int t = blockIdx.x, tid = threadIdx.x;
    float4 v = ((const float4*)(A + (size_t)t * Dz))[tid];
    float4 w = ((const float4*)(Bb + (size_t)t * Dz))[tid];
    v.x += w.x; v.y += w.y; v.z += w.z; v.w += w.w;
    float s = v.x + v.y + v.z + v.w;
    float q = v.x * v.x + v.y * v.y + v.z * v.z + v.w * v.w;
    s = warpsum(s); q = warpsum(q);
    __shared__ float ss[8], sq[8];
    int wid = tid >> 5;
    if ((tid & 31) == 0) { ss[wid] = s; sq[wid] = q; }
    __syncthreads();
    float S = 0.f, Q = 0.f;
    #pragma unroll
    for (int i = 0; i < 8; i++) { S += ss[i]; Q += sq[i]; }
    float mean = S * (1.f / Dz);
    float var  = Q * (1.f / Dz) - mean * mean;
    float rstd = rsqrtf(var + 1e-5f);
    float4 gg = ((const float4*)g)[tid];
    float4 bb = ((const float4*)be)[tid];
    float4 o;
    o.x = (v.x - mean) * rstd * gg.x + bb.x;
    o.y = (v.y - mean) * rstd * gg.y + bb.y;
    o.z = (v.z - mean) * rstd * gg.z + bb.z;
    o.w = (v.w - mean) * rstd * gg.w + bb.w;
    ((float4*)(out + (size_t)t * Dz))[tid] = o;
    uint32_t h0, l0, h1, l1;
    split2(o.x, o.y, h0, l0);
    split2(o.z, o.w, h1, l1);
    ((uint2*)(g_X1bH + (size_t)t * Dz))[tid] = make_uint2(h0, h1);
    ((uint2*)(g_X1bL + (size_t)t * Dz))[tid] = make_uint2(l0, l1);
}

__global__ void k_ln_add3(const float* __restrict__ A,
                          const float* __restrict__ g, const float* __restrict__ be,
                          float* __restrict__ out) {
    int t = blockIdx.x, tid = threadIdx.x;
    float4 v  = ((const float4*)(A + (size_t)t * Dz))[tid];
    float4 y0 = ((const float4*)(g_YB + (size_t)t * 2 * Dz))[tid];
    float4 y1 = ((const float4*)(g_YB + (size_t)t * 2 * Dz + Dz))[tid];
    v.x += y0.x + y1.x; v.y += y0.y + y1.y;
    v.z += y0.z + y1.z; v.w += y0.w + y1.w;
    float s = v.x + v.y + v.z + v.w;
    float q = v.x * v.x + v.y * v.y + v.z * v.z + v.w * v.w;
    s = warpsum(s); q = warpsum(q);
    __shared__ float ss[8], sq[8];
    int wid = tid >> 5;
    if ((tid & 31) == 0) { ss[wid] = s; sq[wid] = q; }
    __syncthreads();
    float S = 0.f, Q = 0.f;
    #pragma unroll
    for (int i = 0; i < 8; i++) { S += ss[i]; Q += sq[i]; }
    float mean = S * (1.f / Dz);
    float var  = Q * (1.f / Dz) - mean * mean;
    float rstd = rsqrtf(var + 1e-5f);
    float4 gg = ((const float4*)g)[tid];
    float4 bb = ((const float4*)be)[tid];
    float4 o;
    o.x = (v.x - mean) * rstd * gg.x + bb.x;
    o.y = (v.y - mean) * rstd * gg.y + bb.y;
    o.z = (v.z - mean) * rstd * gg.z + bb.z;
    o.w = (v.w - mean) * rstd * gg.w + bb.w;
    ((float4*)(out + (size_t)t * Dz))[tid] = o;
}

// ---------------- MoE routing ---------------------------------------------
__global__ void k_gate(const float* __restrict__ gw, const float* __restrict__ gb) {
    int t = blockIdx.x * 8 + (threadIdx.x >> 5);
    int lane = threadIdx.x & 31;
    float acc[En] = {};
    const float* xr = g_X1 + (size_t)t * Dz;
    for (int d = lane; d < Dz; d += 32) {
        float xv = xr[d];
        #pragma unroll
        for (int e = 0; e < En; e++) acc[e] += xv * gw[d * En + e];
    }
    #pragma unroll
    for (int e = 0; e < En; e++) acc[e] = warpsum(acc[e]);
    if (lane == 0) {
        #pragma unroll
        for (int e = 0; e < En; e++) acc[e] += gb[e];
        int e0 = 0; float b0 = acc[0];
        #pragma unroll
        for (int e = 1; e < En; e++) if (acc[e] > b0) { b0 = acc[e]; e0 = e; }
        int e1 = -1; float b1v = -1e30f;
        #pragma unroll
        for (int e = 0; e < En; e++)
            if (e != e0 && acc[e] > b1v) { b1v = acc[e]; e1 = e; }
        float x1 = expf(b1v - b0);
        float inv = 1.f / (1.f + x1);
        g_te[t][0] = e0; g_te[t][1] = e1;
        g_tw[t][0] = inv; g_tw[t][1] = x1 * inv;
        atomicAdd(&g_counts[e0], 1);
        atomicAdd(&g_counts[e1], 1);
    }
}

__global__ void k_offsets() {
    if (threadIdx.x == 0) {
        int off = 0;
        for (int e = 0; e < En; e++) {
            g_offsets[e] = off;
            off += ((g_counts[e] + 127) >> 7) << 7;
            g_cursor[e] = 0;
        }
    }
}

__global__ void k_scatter() {
    int t = blockIdx.x * 256 + threadIdx.x;
    if (t >= Tz) return;
    #pragma unroll
    for (int slot = 0; slot < 2; slot++) {
        int e = g_te[t][slot];
        int pos = atomicAdd(&g_cursor[e], 1);
        int row = g_offsets[e] + pos;
        g_rows_token[row] = t;
        g_rows_w[row] = g_tw[t][slot];
        g_rows_slot[row] = slot;
    }
}

// ---------------- launch ---------------------------------------------------
extern "C" void kernel_launch(void* const* d_in, const int* in_sizes, int n_in,
                              void* d_out, int out_size) {
    const float* x          = (const float*)d_in[0];
    const float* conv_w     = (const float*)d_in[1];
    const float* conv_b     = (const float*)d_in[2];
    const float* in_proj_w  = (const float*)d_in[3];
    const float* in_proj_b  = (const float*)d_in[4];
    const float* out_proj_w = (const float*)d_in[5];
    const float* out_proj_b = (const float*)d_in[6];
    const float* ln1_g      = (const float*)d_in[7];
    const float* ln1_b      = (const float*)d_in[8];
    const float* gate_w     = (const float*)d_in[9];
    const float* gate_b     = (const float*)d_in[10];
    const float* w1         = (const float*)d_in[11];
    const float* b1         = (const float*)d_in[12];
    const float* w2         = (const float*)d_in[13];
    const float* b2         = (const float*)d_in[14];
    const float* ln2_g      = (const float*)d_in[15];
    const float* ln2_b      = (const float*)d_in[16];
    float* out = (float*)d_out;

    float *pXC, *pQKV, *pPROJ, *pX1;
    cudaGetSymbolAddress((void**)&pXC,   g_XC);
    cudaGetSymbolAddress((void**)&pQKV,  g_QKV);
    cudaGetSymbolAddress((void**)&pPROJ, g_PROJ);
    cudaGetSymbolAddress((void**)&pX1,   g_X1);
    u16 *pXbH, *pXbL, *pXCbH, *pXCbL, *pAObH, *pAObL, *pX1bH, *pX1bL, *pHbH, *pHbL;
    u16 *pWINbH, *pWINbL, *pWOUTbH, *pWOUTbL, *pWCVbH, *pWCVbL;
    u16 *pW1bH, *pW1bL, *pW2bH, *pW2bL;
    cudaGetSymbolAddress((void**)&pXbH, g_XbH);   cudaGetSymbolAddress((void**)&pXbL, g_XbL);
    cudaGetSymbolAddress((void**)&pXCbH, g_XCbH); cudaGetSymbolAddress((void**)&pXCbL, g_XCbL);
    cudaGetSymbolAddress((void**)&pAObH, g_AObH); cudaGetSymbolAddress((void**)&pAObL, g_AObL);
    cudaGetSymbolAddress((void**)&pX1bH, g_X1bH); cudaGetSymbolAddress((void**)&pX1bL, g_X1bL);
    cudaGetSymbolAddress((void**)&pHbH, g_HbH);   cudaGetSymbolAddress((void**)&pHbL, g_HbL);
    cudaGetSymbolAddress((void**)&pWINbH, g_WINbH);   cudaGetSymbolAddress((void**)&pWINbL, g_WINbL);
    cudaGetSymbolAddress((void**)&pWOUTbH, g_WOUTbH); cudaGetSymbolAddress((void**)&pWOUTbL, g_WOUTbL);
    cudaGetSymbolAddress((void**)&pWCVbH, g_WCVbH);   cudaGetSymbolAddress((void**)&pWCVbL, g_WCVbL);
    cudaGetSymbolAddress((void**)&pW1bH, g_W1bH);     cudaGetSymbolAddress((void**)&pW1bL, g_W1bL);
    cudaGetSymbolAddress((void**)&pW2bH, g_W2bH);     cudaGetSymbolAddress((void**)&pW2bL, g_W2bL);

    cudaFuncSetAttribute(k_gemm<1,4,3>, cudaFuncAttributeMaxDynamicSharedMemorySize, DSMEM);
    cudaFuncSetAttribute(k_gemm<0,4,0>, cudaFuncAttributeMaxDynamicSharedMemorySize, DSMEM);
    cudaFuncSetAttribute(k_gemm<2,3,1>, cudaFuncAttributeMaxDynamicSharedMemorySize, DSMEM);
    cudaFuncSetAttribute(k_gemm<3,3,2>, cudaFuncAttributeMaxDynamicSharedMemorySize, DSMEM);

    k_zero_counts<<<1, 32>>>();
    // operand prep: f32 -> bf16 hi/lo
    k_cvt<<<(Tz * Dz / 4) / 256, 256>>>(x, pXbH, pXbL, Tz * Dz / 4);
    k_cvt<<<(3 * Dz * Dz / 4) / 256, 256>>>(in_proj_w, pWINbH, pWINbL, 3 * Dz * Dz / 4);
    k_cvt<<<(Dz * Dz / 4) / 256, 256>>>(out_proj_w, pWOUTbH, pWOUTbL, Dz * Dz / 4);
    k_convw<<<dim3(6, Dz), 256>>>(conv_w);
    dim3 tb(32, 8);
    k_wtrans<<<dim3(HIDz / 32, Dz / 32, En), tb>>>(w1, pW1bH, pW1bL, Dz, HIDz);
    k_wtrans<<<dim3(Dz / 32, HIDz / 32, En), tb>>>(w2, pW2bH, pW2bL, HIDz, Dz);
    // conv  (M=T, N=1024, K=3072): f32 XC + XCb pairs
    k_gemm<1,4,3><<<dim3(8, 128), 256, DSMEM>>>(pXbH, pXbL, pWCVbH, pWCVbL,
                                                conv_b, pXC, 3 * Dz, Dz);
    // qkv   (M=T, N=3072, K=1024)
    k_gemm<0,4,0><<<dim3(24, 128), 256, DSMEM>>>(pXCbH, pXCbL, pWINbH, pWINbL,
                                                 in_proj_b, pQKV, Dz, 3 * Dz);
    // attention (tiny seq=B=4) -> AOb pairs
    k_attn<<<(Sz * Hn) / 8, 256>>>();
    // out_proj (M=T, N=1024, K=1024)
    k_gemm<0,4,0><<<dim3(8, 128), 256, DSMEM>>>(pAObH, pAObL, pWOUTbH, pWOUTbL,
                                                out_proj_b, pPROJ, Dz, Dz);
    // residual + LN1 (emits X1 f32 + pairs)
    k_ln_add2<<<Tz, 256>>>(pXC, pPROJ, ln1_g, ln1_b, pX1);
    // MoE routing
    k_gate<<<Tz / 8, 256>>>(gate_w, gate_b);
    k_offsets<<<1, 32>>>();
    k_scatter<<<Tz / 256, 256>>>();
    // grouped expert GEMMs
    k_gemm<2,3,1><<<dim3(32, 128, En), 256, DSMEM>>>(pX1bH, pX1bL, pW1bH, pW1bL,
                                                     b1, nullptr, Dz, 0);
    k_gemm<3,3,2><<<dim3(8, 128, En), 256, DSMEM>>>(pHbH, pHbL, pW2bH, pW2bL,
                                                    b2, nullptr, HIDz, 0);
    // residual + LN2 -> output
    k_ln_add3<<<Tz, 256>>>(pX1, ln2_g, ln2_b, out);
}